// round 14
// baseline (speedup 1.0000x reference)
#include <cuda_runtime.h>
#include <cuda_bf16.h>
#include <cstdint>
#include <cstddef>

// ---------------- problem constants (fixed shapes) ----------------
#define NB 8
#define NQ 300
#define NM 100
#define NCLS 81
#define HW 16384
#define QPAD 384           // 4 tiles of 96 queries
#define MPAD 128           // gt padded to 128 for N dim
#define KSPLIT 4
#define KLEN (HW / KSPLIT) // 4096 bf16 per K-split
#define BK 64              // K tile (bf16 elems) = 128B row
#define KT (KLEN / BK)     // 64 iterations
#define MT 96              // M tile rows (queries per CTA)
#define NQT 4              // number of Q tiles

// ---------------- static device scratch (no allocations allowed) ----------------
__device__ __nv_bfloat16 g_PM[(size_t)NB * QPAD * HW];   // sigmoid(pred_masks), bf16
__device__ __nv_bfloat16 g_GM[(size_t)NB * MPAD * HW];   // gt_masks, bf16
__device__ float g_NUM[(size_t)KSPLIT * NB * NQ * NM];   // partial dot products
__device__ float g_pm_sum[NB * NQ];
__device__ float g_gm_sum[NB * NM];

__device__ __forceinline__ float fast_sigmoid(float x) {
    float t;
    asm("tanh.approx.f32 %0, %1;" : "=f"(t) : "f"(x * 0.5f));
    return fmaf(t, 0.5f, 0.5f);
}

// ===================== kernel 1: fused converts, 64B per thread-iter =====================
__global__ void __launch_bounds__(256) k_convert(const float* __restrict__ pm,
                                                 const float* __restrict__ gm) {
    int blk = blockIdx.x;
    float sum = 0.f;
    if (blk < NB * NQ) {                      // ---- pred path ----
        int b = blk / NQ, q = blk - b * NQ;
        const float4* src = reinterpret_cast<const float4*>(pm + (size_t)blk * HW);
        uint4* dst = reinterpret_cast<uint4*>(g_PM + ((size_t)b * QPAD + q) * HW);
        for (int i = threadIdx.x; i < HW / 16; i += 256) {
            float4 v0 = src[4 * i];
            float4 v1 = src[4 * i + 1];
            float4 v2 = src[4 * i + 2];
            float4 v3 = src[4 * i + 3];
            float s0 = fast_sigmoid(v0.x), s1 = fast_sigmoid(v0.y);
            float s2 = fast_sigmoid(v0.z), s3 = fast_sigmoid(v0.w);
            float s4 = fast_sigmoid(v1.x), s5 = fast_sigmoid(v1.y);
            float s6 = fast_sigmoid(v1.z), s7 = fast_sigmoid(v1.w);
            float s8 = fast_sigmoid(v2.x), s9 = fast_sigmoid(v2.y);
            float sa = fast_sigmoid(v2.z), sb = fast_sigmoid(v2.w);
            float sc = fast_sigmoid(v3.x), sd = fast_sigmoid(v3.y);
            float se = fast_sigmoid(v3.z), sf = fast_sigmoid(v3.w);
            sum += (((s0 + s1) + (s2 + s3)) + ((s4 + s5) + (s6 + s7)))
                 + (((s8 + s9) + (sa + sb)) + ((sc + sd) + (se + sf)));
            __nv_bfloat162 p0 = __floats2bfloat162_rn(s0, s1);
            __nv_bfloat162 p1 = __floats2bfloat162_rn(s2, s3);
            __nv_bfloat162 p2 = __floats2bfloat162_rn(s4, s5);
            __nv_bfloat162 p3 = __floats2bfloat162_rn(s6, s7);
            __nv_bfloat162 p4 = __floats2bfloat162_rn(s8, s9);
            __nv_bfloat162 p5 = __floats2bfloat162_rn(sa, sb);
            __nv_bfloat162 p6 = __floats2bfloat162_rn(sc, sd);
            __nv_bfloat162 p7 = __floats2bfloat162_rn(se, sf);
            dst[2 * i] = make_uint4(*reinterpret_cast<uint32_t*>(&p0),
                                    *reinterpret_cast<uint32_t*>(&p1),
                                    *reinterpret_cast<uint32_t*>(&p2),
                                    *reinterpret_cast<uint32_t*>(&p3));
            dst[2 * i + 1] = make_uint4(*reinterpret_cast<uint32_t*>(&p4),
                                        *reinterpret_cast<uint32_t*>(&p5),
                                        *reinterpret_cast<uint32_t*>(&p6),
                                        *reinterpret_cast<uint32_t*>(&p7));
        }
    } else {                                  // ---- gt path ----
        int bm = blk - NB * NQ;
        int b = bm / NM, m = bm - b * NM;
        const float4* src = reinterpret_cast<const float4*>(gm + (size_t)bm * HW);
        uint4* dst = reinterpret_cast<uint4*>(g_GM + ((size_t)b * MPAD + m) * HW);
        for (int i = threadIdx.x; i < HW / 16; i += 256) {
            float4 v0 = src[4 * i];
            float4 v1 = src[4 * i + 1];
            float4 v2 = src[4 * i + 2];
            float4 v3 = src[4 * i + 3];
            sum += (((v0.x + v0.y) + (v0.z + v0.w)) + ((v1.x + v1.y) + (v1.z + v1.w)))
                 + (((v2.x + v2.y) + (v2.z + v2.w)) + ((v3.x + v3.y) + (v3.z + v3.w)));
            __nv_bfloat162 p0 = __floats2bfloat162_rn(v0.x, v0.y);
            __nv_bfloat162 p1 = __floats2bfloat162_rn(v0.z, v0.w);
            __nv_bfloat162 p2 = __floats2bfloat162_rn(v1.x, v1.y);
            __nv_bfloat162 p3 = __floats2bfloat162_rn(v1.z, v1.w);
            __nv_bfloat162 p4 = __floats2bfloat162_rn(v2.x, v2.y);
            __nv_bfloat162 p5 = __floats2bfloat162_rn(v2.z, v2.w);
            __nv_bfloat162 p6 = __floats2bfloat162_rn(v3.x, v3.y);
            __nv_bfloat162 p7 = __floats2bfloat162_rn(v3.z, v3.w);
            dst[2 * i] = make_uint4(*reinterpret_cast<uint32_t*>(&p0),
                                    *reinterpret_cast<uint32_t*>(&p1),
                                    *reinterpret_cast<uint32_t*>(&p2),
                                    *reinterpret_cast<uint32_t*>(&p3));
            dst[2 * i + 1] = make_uint4(*reinterpret_cast<uint32_t*>(&p4),
                                        *reinterpret_cast<uint32_t*>(&p5),
                                        *reinterpret_cast<uint32_t*>(&p6),
                                        *reinterpret_cast<uint32_t*>(&p7));
        }
    }
    for (int o = 16; o; o >>= 1) sum += __shfl_down_sync(0xffffffffu, sum, o);
    __shared__ float ws[8];
    if ((threadIdx.x & 31) == 0) ws[threadIdx.x >> 5] = sum;
    __syncthreads();
    if (threadIdx.x == 0) {
        float t = 0.f;
        #pragma unroll
        for (int w = 0; w < 8; ++w) t += ws[w];
        if (blk < NB * NQ) g_pm_sum[blk] = t;
        else g_gm_sum[blk - NB * NQ] = t;
    }
}

// ===================== kernel 2: mma.sync bf16 GEMM, 96-row tiles, 3-stage =====================
#define A_TILE (MT * 128)         // 12288 bytes
#define B_TILE (128 * 128)        // 16384 bytes
#define GEMM_SMEM (3 * (A_TILE + B_TILE))   // 86016

__device__ __forceinline__ uint32_t sw128(uint32_t off) {
    return off ^ ((off >> 3) & 0x70);
}

__device__ __forceinline__ void cp_tileA(const __nv_bfloat16* __restrict__ src,
                                         uint32_t dstBase) {
    int t = threadIdx.x;
    #pragma unroll
    for (int s = 0; s < 3; ++s) {
        int i = t + s * 256;                  // 0..767 (96 rows x 8 chunks)
        int row = i >> 3, c16 = i & 7;
        unsigned long long g =
            __cvta_generic_to_global(src + (size_t)row * HW + c16 * 8);
        uint32_t off = sw128((uint32_t)(row * 128 + c16 * 16));
        asm volatile("cp.async.cg.shared.global [%0], [%1], 16;"
                     :: "r"(dstBase + off), "l"(g));
    }
}

__device__ __forceinline__ void cp_tileB(const __nv_bfloat16* __restrict__ src,
                                         uint32_t dstBase) {
    int t = threadIdx.x;
    #pragma unroll
    for (int s = 0; s < 4; ++s) {
        int i = t + s * 256;                  // 0..1023 (128 rows x 8 chunks)
        int row = i >> 3, c16 = i & 7;
        unsigned long long g =
            __cvta_generic_to_global(src + (size_t)row * HW + c16 * 8);
        uint32_t off = sw128((uint32_t)(row * 128 + c16 * 16));
        asm volatile("cp.async.cg.shared.global [%0], [%1], 16;"
                     :: "r"(dstBase + off), "l"(g));
    }
}

__global__ void __launch_bounds__(256) k_mask_gemm() {
    extern __shared__ char smem[];
    uint32_t sA = (uint32_t)__cvta_generic_to_shared(smem);
    uint32_t sB = sA + 3 * A_TILE;

    int tid = threadIdx.x, lane = tid & 31, warp = tid >> 5;
    int wm = warp & 1, wn = warp >> 1;        // 2 x 4 warp grid
    int warpRow = wm * 48, warpCol = wn * 32;

    int tile = blockIdx.x, b = blockIdx.y, ks = blockIdx.z;
    int q0 = tile * MT;

    const __nv_bfloat16* Abase = g_PM + ((size_t)b * QPAD + q0) * HW + (size_t)ks * KLEN;
    const __nv_bfloat16* Bbase = g_GM + (size_t)b * MPAD * HW + (size_t)ks * KLEN;

    float acc[3][4][4];
    #pragma unroll
    for (int i = 0; i < 3; ++i)
        #pragma unroll
        for (int j = 0; j < 4; ++j)
            #pragma unroll
            for (int r = 0; r < 4; ++r) acc[i][j][r] = 0.f;

    cp_tileA(Abase, sA);
    cp_tileB(Bbase, sB);
    asm volatile("cp.async.commit_group;");
    cp_tileA(Abase + BK, sA + A_TILE);
    cp_tileB(Bbase + BK, sB + B_TILE);
    asm volatile("cp.async.commit_group;");
    asm volatile("cp.async.wait_group 1;");
    __syncthreads();

    int rA = warpRow + (lane & 15);
    int cAsel = lane >> 4;
    int rB = warpCol + (lane & 7);
    int cBsel = (lane >> 3) & 1;

    int st = 0, pst = 2;
    for (int kt = 0; kt < KT; ++kt) {
        int pf = kt + 2;
        if (pf < KT) {
            cp_tileA(Abase + (size_t)pf * BK, sA + pst * A_TILE);
            cp_tileB(Bbase + (size_t)pf * BK, sB + pst * B_TILE);
            asm volatile("cp.async.commit_group;");
        }
        uint32_t a0 = sA + st * A_TILE;
        uint32_t b0 = sB + st * B_TILE;

        #pragma unroll
        for (int kk = 0; kk < 4; ++kk) {
            uint32_t af[3][4], bf[4][2];
            #pragma unroll
            for (int mt = 0; mt < 3; ++mt) {
                uint32_t addr = a0 + sw128((uint32_t)((rA + mt * 16) * 128
                                                      + (kk * 2 + cAsel) * 16));
                asm volatile("ldmatrix.sync.aligned.m8n8.x4.shared.b16 "
                             "{%0,%1,%2,%3}, [%4];"
                             : "=r"(af[mt][0]), "=r"(af[mt][1]),
                               "=r"(af[mt][2]), "=r"(af[mt][3]) : "r"(addr));
            }
            #pragma unroll
            for (int nt = 0; nt < 4; ++nt) {
                uint32_t addr = b0 + sw128((uint32_t)((rB + nt * 8) * 128
                                                      + (kk * 2 + cBsel) * 16));
                asm volatile("ldmatrix.sync.aligned.m8n8.x2.shared.b16 "
                             "{%0,%1}, [%2];"
                             : "=r"(bf[nt][0]), "=r"(bf[nt][1]) : "r"(addr));
            }
            #pragma unroll
            for (int mt = 0; mt < 3; ++mt)
                #pragma unroll
                for (int nt = 0; nt < 4; ++nt) {
                    asm volatile(
                        "mma.sync.aligned.m16n8k16.row.col.f32.bf16.bf16.f32 "
                        "{%0,%1,%2,%3}, {%4,%5,%6,%7}, {%8,%9}, {%0,%1,%2,%3};"
                        : "+f"(acc[mt][nt][0]), "+f"(acc[mt][nt][1]),
                          "+f"(acc[mt][nt][2]), "+f"(acc[mt][nt][3])
                        : "r"(af[mt][0]), "r"(af[mt][1]),
                          "r"(af[mt][2]), "r"(af[mt][3]),
                          "r"(bf[nt][0]), "r"(bf[nt][1]));
                }
        }
        if (kt + 1 < KT) {
            if (pf < KT) { asm volatile("cp.async.wait_group 1;"); }
            else         { asm volatile("cp.async.wait_group 0;"); }
        }
        __syncthreads();
        st = (st == 2) ? 0 : st + 1;
        pst = (pst == 2) ? 0 : pst + 1;
    }

    float* dst = g_NUM + ((size_t)ks * NB + b) * NQ * NM;
    int rowInTile = lane >> 2;
    int colInTile = (lane & 3) * 2;
    #pragma unroll
    for (int mt = 0; mt < 3; ++mt) {
        #pragma unroll
        for (int nt = 0; nt < 4; ++nt) {
            int qb = q0 + warpRow + mt * 16 + rowInTile;
            int mb = warpCol + nt * 8 + colInTile;
            #pragma unroll
            for (int r = 0; r < 4; ++r) {
                int q = qb + ((r >> 1) ? 8 : 0);
                int m = mb + (r & 1);
                if (q < NQ && m < NM)
                    dst[(size_t)q * NM + m] = acc[mt][nt][r];
            }
        }
    }
}

// ===================== kernel 3: assemble full cost matrix =====================
__global__ void __launch_bounds__(128) k_finalize(const float* __restrict__ logits,
                                                  const float* __restrict__ pboxes,
                                                  const int* __restrict__ glabels,
                                                  const float* __restrict__ gboxes,
                                                  float* __restrict__ out) {
    int q = blockIdx.x, b = blockIdx.y;
    int tid = threadIdx.x;
    __shared__ float probs[NCLS];
    __shared__ float red[128];

    const float* lg = logits + ((size_t)b * NQ + q) * NCLS;
    float x = (tid < NCLS) ? lg[tid] : -3.0e38f;
    red[tid] = x; __syncthreads();
    #pragma unroll
    for (int s = 64; s > 0; s >>= 1) { if (tid < s) red[tid] = fmaxf(red[tid], red[tid + s]); __syncthreads(); }
    float mx = red[0]; __syncthreads();
    float e = (tid < NCLS) ? __expf(x - mx) : 0.f;
    red[tid] = e; __syncthreads();
    #pragma unroll
    for (int s = 64; s > 0; s >>= 1) { if (tid < s) red[tid] += red[tid + s]; __syncthreads(); }
    float inv = 1.f / red[0];
    if (tid < NCLS) probs[tid] = e * inv;
    __syncthreads();

    const float* pb = pboxes + ((size_t)b * NQ + q) * 4;
    float px1 = pb[0], py1 = pb[1], px2 = pb[2], py2 = pb[3];
    float pa = (px2 - px1) * (py2 - py1);
    float psum = g_pm_sum[b * NQ + q];
    const size_t NSTR = (size_t)NB * NQ * NM;

    for (int m = tid; m < NM; m += 128) {
        int lbl = glabels[b * NM + m];
        float cclass = -probs[lbl];
        const float* gb = gboxes + ((size_t)b * NM + m) * 4;
        float gx1 = gb[0], gy1 = gb[1], gx2 = gb[2], gy2 = gb[3];
        float l1 = fabsf(px1 - gx1) + fabsf(py1 - gy1) + fabsf(px2 - gx2) + fabsf(py2 - gy2);
        float iw = fmaxf(fminf(px2, gx2) - fmaxf(px1, gx1), 0.f);
        float ih = fmaxf(fminf(py2, gy2) - fmaxf(py1, gy1), 0.f);
        float inter = iw * ih;
        float ga = (gx2 - gx1) * (gy2 - gy1);
        float uni = pa + ga - inter;
        float iou = inter / (uni + 1e-6f);
        float ew = fmaxf(fmaxf(px2, gx2) - fminf(px1, gx1), 0.f);
        float eh = fmaxf(fmaxf(py2, gy2) - fminf(py1, gy1), 0.f);
        float am = ew * eh;
        float giou = iou - (am - uni) / (am + 1e-6f);
        size_t ni = ((size_t)b * NQ + q) * NM + m;
        float dot = g_NUM[ni] + g_NUM[NSTR + ni] + g_NUM[2 * NSTR + ni] + g_NUM[3 * NSTR + ni];
        float den = psum + g_gm_sum[b * NM + m];
        float cmask = 1.f - (2.f * dot) / (den + 1e-6f);
        out[ni] = cclass + 5.f * (l1 - giou) + 2.f * cmask;
    }
}

// ===================== kernel 4: JV solver (round-12 exact version, v=0 init) ==========
#define HUNG_THREADS 512
#define NQP 301                   // padded cost stride
#define HUNG_SMEM (NM * 4 + NM * NQP * 4 + NQ * 8 + NM * 8 + NM * 4)
#define NSLOT 10

__device__ __forceinline__ uint32_t fkey(float f) {
    uint32_t u = __float_as_uint(f);
    return (u & 0x80000000u) ? ~u : (u | 0x80000000u);
}
__device__ __forceinline__ float funkey(uint32_t k) {
    uint32_t u = (k & 0x80000000u) ? (k & 0x7fffffffu) : ~k;
    return __uint_as_float(u);
}
__device__ __forceinline__ uint32_t redux_min(uint32_t v) {
    uint32_t d;
    asm volatile("redux.sync.min.u32 %0, %1, 0xffffffff;" : "=r"(d) : "r"(v));
    return d;
}

__global__ void __launch_bounds__(HUNG_THREADS) k_hungarian(float* __restrict__ out, int out_size) {
    extern __shared__ char sm[];
    float* u    = reinterpret_cast<float*>(sm);               // [100]
    float* cost = u + NM;                                     // [100][301] transposed
    int* p      = reinterpret_cast<int*>(cost + NM * NQP);    // [300]
    int* way    = p + NQ;                                     // [300]
    int* flA    = way + NQ;                                   // [100]
    int* flB    = flA + NM;                                   // [100]
    int* rowarg = flB + NM;                                   // [100]

    int b = blockIdx.x;
    int tid = threadIdx.x;
    const int lane = tid & 31;
    const int warp = tid >> 5;
    const float* C = out + (size_t)b * NQ * NM;

    for (int idx = tid; idx < NM * NQ; idx += HUNG_THREADS) {
        int q = idx / NM, m = idx - q * NM;
        cost[m * NQP + q] = C[idx];
    }
    for (int j = tid; j < NQ; j += HUNG_THREADS) p[j] = -1;
    __syncthreads();

    // ---- phase 1 (parallel): per-row minima across 16 warps ----
    const bool valid9 = (lane < 12);          // col 288..299 only
    for (int i = warp; i < NM; i += 16) {
        const float* crow = cost + i * NQP;
        float bv = 3.0e38f; int bi = 0x7fffffff;
        #pragma unroll
        for (int s = 0; s < NSLOT; ++s) {
            int col = s * 32 + lane;
            if (s < 9 || valid9) {
                float v = crow[col];
                if (v < bv) { bv = v; bi = col; }
            }
        }
        uint32_t k = fkey(bv);
        uint32_t mk = redux_min(k);
        int jstar = (int)redux_min((k == mk) ? (uint32_t)bi : 0xffffffffu);
        if (lane == 0) { u[i] = funkey(mk); rowarg[i] = jstar; }
    }
    __syncthreads();
    if (tid >= 32) return;

    float vv[NSLOT], minv[NSLOT];
    #pragma unroll
    for (int s = 0; s < NSLOT; ++s) vv[s] = 0.0f;

    // ---- greedy seed ----
    int nfree = 0;
    if (lane == 0) {
        for (int i = 0; i < NM; ++i) {
            int js = rowarg[i];
            if (p[js] == -1) p[js] = i;
            else flA[nfree++] = i;
        }
    }
    __syncwarp();
    nfree = __shfl_sync(0xffffffffu, nfree, 0);

    // ---- phase 2: augmenting row reduction (<=6 passes), shortened chain ----
    int* cur = flA; int* nxt = flB;
    for (int pass = 0; pass < 6 && nfree > 0; ++pass) {
        int nnew = 0;
        for (int k = 0; k < nfree; ++k) {
            int i = cur[k];
            for (;;) {
                const float* crow = cost + i * NQP;
                uint32_t kk[NSLOT];
                uint32_t m1k = 0xffffffffu, m2k = 0xffffffffu; int c1 = 0x7fffffff;
                #pragma unroll
                for (int s = 0; s < NSLOT; ++s) {
                    int col = s * 32 + lane;
                    uint32_t kv = 0xffffffffu;
                    if (s < 9 || valid9) kv = fkey(crow[col] - vv[s]);
                    kk[s] = kv;
                    if (kv < m1k) { m2k = m1k; m1k = kv; c1 = col; }
                    else if (kv < m2k) { m2k = kv; }
                }
                uint32_t u1k = redux_min(m1k);
                int j1 = (int)redux_min((m1k == u1k) ? (uint32_t)c1 : 0xffffffffu);
                uint32_t u2k = redux_min((m1k == u1k) ? m2k : m1k);
                unsigned tb = __ballot_sync(0xffffffffu, m1k == u1k);
                unsigned db = __ballot_sync(0xffffffffu, (m1k == u1k) && (m2k == u1k));
                if ((tb & (tb - 1)) || db) u2k = u1k;
                float u1 = funkey(u1k), u2 = funkey(u2k);
                bool strict = (u1k < u2k);
                int j2 = 0;
                if (!strict) {
                    int cbest = 0x7fffffff;
                    #pragma unroll
                    for (int s = 0; s < NSLOT; ++s) {
                        int col = s * 32 + lane;
                        if (kk[s] == u2k && col != j1 && col < cbest) cbest = col;
                    }
                    j2 = (int)redux_min((uint32_t)cbest);
                }

                int pack = 0;
                if (lane == 0) {
                    int jt = j1;
                    if (!strict) {
                        int pj1 = p[j1], pj2 = p[j2];
                        if (pj1 != -1 && pj2 == -1) jt = j2;
                    }
                    int ev = p[jt];
                    u[i] = u2; p[jt] = i;
                    pack = (jt << 9) | (ev + 1);
                }
                pack = __shfl_sync(0xffffffffu, pack, 0);
                int jt = pack >> 9;
                int ev = (pack & 511) - 1;
                if (strict && lane == (jt & 31)) vv[jt >> 5] -= (u2 - u1);

                if (ev == -1) break;
                if (strict) { i = ev; continue; }
                if (lane == 0) nxt[nnew] = ev;
                ++nnew;
                break;
            }
        }
        __syncwarp();
        int* t = cur; cur = nxt; nxt = t;
        nfree = nnew;
    }

    // ---- phase 3: shortest augmenting path for the remainder ----
    for (int fidx = 0; fidx < nfree; ++fidx) {
        int i = cur[fidx];
        unsigned usedmask = 0;
        #pragma unroll
        for (int s = 0; s < NSLOT; ++s) minv[s] = 3.0e38f;
        int cr = i, j0 = -1;

        while (true) {
            float ucr = u[cr];
            const float* crow = cost + cr * NQP;
            float bv = 3.0e38f; int bi = 0x7fffffff;
            #pragma unroll
            for (int s = 0; s < NSLOT; ++s) {
                int col = s * 32 + lane;
                bool ok = (s < 9 || valid9) && !((usedmask >> s) & 1u);
                if (ok) {
                    float cv = crow[col] - ucr - vv[s];
                    if (cv < minv[s]) { minv[s] = cv; way[col] = j0; }
                    if (minv[s] < bv) { bv = minv[s]; bi = col; }
                }
            }
            uint32_t k = fkey(bv);
            uint32_t mk = redux_min(k);
            float delta = funkey(mk);
            int j1 = (int)redux_min((k == mk) ? (uint32_t)bi : 0xffffffffu);

            #pragma unroll
            for (int s = 0; s < NSLOT; ++s) {
                int col = s * 32 + lane;
                if (s < 9 || valid9) {
                    if ((usedmask >> s) & 1u) {
                        u[p[col]] += delta;
                        vv[s] -= delta;
                    } else {
                        minv[s] -= delta;
                    }
                }
            }
            if (lane == 0) u[i] += delta;
            if (lane == (j1 & 31)) usedmask |= 1u << (j1 >> 5);
            j0 = j1;
            cr = p[j1];
            __syncwarp();
            if (cr == -1) break;
        }

        if (lane == 0) {
            int j = j0;
            while (j != -1) {
                int jp = way[j];
                p[j] = (jp != -1) ? p[jp] : i;
                j = jp;
            }
        }
        __syncwarp();
    }

    // ---- output: parallel compaction (ballot prefix ranks) ----
    if (out_size >= NB * NQ * NM + 2 * NB * NM) {
        float* pi = out + (size_t)NB * NQ * NM + (size_t)b * NM;
        float* gi = pi + (size_t)NB * NM;
        int base = 0;
        #pragma unroll
        for (int blk0 = 0; blk0 < NQ; blk0 += 32) {
            int col = blk0 + lane;
            int pv = (col < NQ) ? p[col] : -1;
            unsigned mask = __ballot_sync(0xffffffffu, pv >= 0);
            if (pv >= 0) {
                int r = base + __popc(mask & ((1u << lane) - 1u));
                pi[r] = (float)col;
                gi[r] = (float)pv;
            }
            base += __popc(mask);
        }
    }
}

// ===================== launch =====================
extern "C" void kernel_launch(void* const* d_in, const int* in_sizes, int n_in,
                              void* d_out, int out_size) {
    const float* pred_logits = (const float*)d_in[0];
    const float* pred_boxes  = (const float*)d_in[1];
    const float* pred_masks  = (const float*)d_in[2];
    const int*   gt_labels   = (const int*)d_in[3];
    const float* gt_boxes    = (const float*)d_in[4];
    const float* gt_masks    = (const float*)d_in[5];
    float* out = (float*)d_out;

    k_convert<<<NB * NQ + NB * NM, 256>>>(pred_masks, gt_masks);

    cudaFuncSetAttribute(k_mask_gemm, cudaFuncAttributeMaxDynamicSharedMemorySize, GEMM_SMEM);
    k_mask_gemm<<<dim3(NQT, NB, KSPLIT), 256, GEMM_SMEM>>>();

    k_finalize<<<dim3(NQ, NB), 128>>>(pred_logits, pred_boxes, gt_labels, gt_boxes, out);

    cudaFuncSetAttribute(k_hungarian, cudaFuncAttributeMaxDynamicSharedMemorySize, HUNG_SMEM);
    k_hungarian<<<NB, HUNG_THREADS, HUNG_SMEM>>>(out, out_size);
}

// round 15
// speedup vs baseline: 1.0241x; 1.0241x over previous
#include <cuda_runtime.h>
#include <cuda_bf16.h>
#include <cstdint>
#include <cstddef>

// ---------------- problem constants (fixed shapes) ----------------
#define NB 8
#define NQ 300
#define NM 100
#define NCLS 81
#define HW 16384
#define QPAD 384           // 4 tiles of 96 queries
#define MPAD 128           // gt padded to 128 for N dim
#define KSPLIT 4
#define KLEN (HW / KSPLIT) // 4096 bf16 per K-split
#define BK 64              // K tile (bf16 elems) = 128B row
#define KT (KLEN / BK)     // 64 iterations
#define MT 96              // M tile rows (queries per CTA)
#define NQT 4              // number of Q tiles

// ---------------- static device scratch (no allocations allowed) ----------------
__device__ __nv_bfloat16 g_PM[(size_t)NB * QPAD * HW];   // sigmoid(pred_masks), bf16
__device__ __nv_bfloat16 g_GM[(size_t)NB * MPAD * HW];   // gt_masks, bf16
__device__ float g_NUM[(size_t)KSPLIT * NB * NQ * NM];   // partial dot products
__device__ float g_pm_sum[NB * NQ];
__device__ float g_gm_sum[NB * NM];

__device__ __forceinline__ float fast_sigmoid(float x) {
    float t;
    asm("tanh.approx.f32 %0, %1;" : "=f"(t) : "f"(x * 0.5f));
    return fmaf(t, 0.5f, 0.5f);
}

// ===================== kernel 1: fused converts (pred sigmoid + gt) =====================
__global__ void __launch_bounds__(256) k_convert(const float* __restrict__ pm,
                                                 const float* __restrict__ gm) {
    int blk = blockIdx.x;
    float sum = 0.f;
    if (blk < NB * NQ) {                      // ---- pred path ----
        int b = blk / NQ, q = blk - b * NQ;
        const float4* src = reinterpret_cast<const float4*>(pm + (size_t)blk * HW);
        uint4* dst = reinterpret_cast<uint4*>(g_PM + ((size_t)b * QPAD + q) * HW);
        for (int i = threadIdx.x; i < HW / 8; i += 256) {
            float4 v0 = src[2 * i];
            float4 v1 = src[2 * i + 1];
            float s0 = fast_sigmoid(v0.x), s1 = fast_sigmoid(v0.y);
            float s2 = fast_sigmoid(v0.z), s3 = fast_sigmoid(v0.w);
            float s4 = fast_sigmoid(v1.x), s5 = fast_sigmoid(v1.y);
            float s6 = fast_sigmoid(v1.z), s7 = fast_sigmoid(v1.w);
            sum += ((s0 + s1) + (s2 + s3)) + ((s4 + s5) + (s6 + s7));
            __nv_bfloat162 p0 = __floats2bfloat162_rn(s0, s1);
            __nv_bfloat162 p1 = __floats2bfloat162_rn(s2, s3);
            __nv_bfloat162 p2 = __floats2bfloat162_rn(s4, s5);
            __nv_bfloat162 p3 = __floats2bfloat162_rn(s6, s7);
            dst[i] = make_uint4(*reinterpret_cast<uint32_t*>(&p0),
                                *reinterpret_cast<uint32_t*>(&p1),
                                *reinterpret_cast<uint32_t*>(&p2),
                                *reinterpret_cast<uint32_t*>(&p3));
        }
    } else {                                  // ---- gt path ----
        int bm = blk - NB * NQ;
        int b = bm / NM, m = bm - b * NM;
        const float4* src = reinterpret_cast<const float4*>(gm + (size_t)bm * HW);
        uint4* dst = reinterpret_cast<uint4*>(g_GM + ((size_t)b * MPAD + m) * HW);
        for (int i = threadIdx.x; i < HW / 8; i += 256) {
            float4 v0 = src[2 * i];
            float4 v1 = src[2 * i + 1];
            sum += ((v0.x + v0.y) + (v0.z + v0.w)) + ((v1.x + v1.y) + (v1.z + v1.w));
            __nv_bfloat162 p0 = __floats2bfloat162_rn(v0.x, v0.y);
            __nv_bfloat162 p1 = __floats2bfloat162_rn(v0.z, v0.w);
            __nv_bfloat162 p2 = __floats2bfloat162_rn(v1.x, v1.y);
            __nv_bfloat162 p3 = __floats2bfloat162_rn(v1.z, v1.w);
            dst[i] = make_uint4(*reinterpret_cast<uint32_t*>(&p0),
                                *reinterpret_cast<uint32_t*>(&p1),
                                *reinterpret_cast<uint32_t*>(&p2),
                                *reinterpret_cast<uint32_t*>(&p3));
        }
    }
    for (int o = 16; o; o >>= 1) sum += __shfl_down_sync(0xffffffffu, sum, o);
    __shared__ float ws[8];
    if ((threadIdx.x & 31) == 0) ws[threadIdx.x >> 5] = sum;
    __syncthreads();
    if (threadIdx.x == 0) {
        float t = 0.f;
        #pragma unroll
        for (int w = 0; w < 8; ++w) t += ws[w];
        if (blk < NB * NQ) g_pm_sum[blk] = t;
        else g_gm_sum[blk - NB * NQ] = t;
    }
}

// ===================== kernel 2: mma.sync bf16 GEMM, 96-row tiles, 3-stage =====================
#define A_TILE (MT * 128)         // 12288 bytes
#define B_TILE (128 * 128)        // 16384 bytes
#define GEMM_SMEM (3 * (A_TILE + B_TILE))   // 86016

__device__ __forceinline__ uint32_t sw128(uint32_t off) {
    return off ^ ((off >> 3) & 0x70);
}

__device__ __forceinline__ void cp_tileA(const __nv_bfloat16* __restrict__ src,
                                         uint32_t dstBase) {
    int t = threadIdx.x;
    #pragma unroll
    for (int s = 0; s < 3; ++s) {
        int i = t + s * 256;                  // 0..767 (96 rows x 8 chunks)
        int row = i >> 3, c16 = i & 7;
        unsigned long long g =
            __cvta_generic_to_global(src + (size_t)row * HW + c16 * 8);
        uint32_t off = sw128((uint32_t)(row * 128 + c16 * 16));
        asm volatile("cp.async.cg.shared.global [%0], [%1], 16;"
                     :: "r"(dstBase + off), "l"(g));
    }
}

__device__ __forceinline__ void cp_tileB(const __nv_bfloat16* __restrict__ src,
                                         uint32_t dstBase) {
    int t = threadIdx.x;
    #pragma unroll
    for (int s = 0; s < 4; ++s) {
        int i = t + s * 256;                  // 0..1023 (128 rows x 8 chunks)
        int row = i >> 3, c16 = i & 7;
        unsigned long long g =
            __cvta_generic_to_global(src + (size_t)row * HW + c16 * 8);
        uint32_t off = sw128((uint32_t)(row * 128 + c16 * 16));
        asm volatile("cp.async.cg.shared.global [%0], [%1], 16;"
                     :: "r"(dstBase + off), "l"(g));
    }
}

__global__ void __launch_bounds__(256) k_mask_gemm() {
    extern __shared__ char smem[];
    uint32_t sA = (uint32_t)__cvta_generic_to_shared(smem);
    uint32_t sB = sA + 3 * A_TILE;

    int tid = threadIdx.x, lane = tid & 31, warp = tid >> 5;
    int wm = warp & 1, wn = warp >> 1;        // 2 x 4 warp grid
    int warpRow = wm * 48, warpCol = wn * 32;

    int tile = blockIdx.x, b = blockIdx.y, ks = blockIdx.z;
    int q0 = tile * MT;

    const __nv_bfloat16* Abase = g_PM + ((size_t)b * QPAD + q0) * HW + (size_t)ks * KLEN;
    const __nv_bfloat16* Bbase = g_GM + (size_t)b * MPAD * HW + (size_t)ks * KLEN;

    float acc[3][4][4];
    #pragma unroll
    for (int i = 0; i < 3; ++i)
        #pragma unroll
        for (int j = 0; j < 4; ++j)
            #pragma unroll
            for (int r = 0; r < 4; ++r) acc[i][j][r] = 0.f;

    cp_tileA(Abase, sA);
    cp_tileB(Bbase, sB);
    asm volatile("cp.async.commit_group;");
    cp_tileA(Abase + BK, sA + A_TILE);
    cp_tileB(Bbase + BK, sB + B_TILE);
    asm volatile("cp.async.commit_group;");
    asm volatile("cp.async.wait_group 1;");
    __syncthreads();

    int rA = warpRow + (lane & 15);
    int cAsel = lane >> 4;
    int rB = warpCol + (lane & 7);
    int cBsel = (lane >> 3) & 1;

    int st = 0, pst = 2;
    for (int kt = 0; kt < KT; ++kt) {
        int pf = kt + 2;
        if (pf < KT) {
            cp_tileA(Abase + (size_t)pf * BK, sA + pst * A_TILE);
            cp_tileB(Bbase + (size_t)pf * BK, sB + pst * B_TILE);
            asm volatile("cp.async.commit_group;");
        }
        uint32_t a0 = sA + st * A_TILE;
        uint32_t b0 = sB + st * B_TILE;

        #pragma unroll
        for (int kk = 0; kk < 4; ++kk) {
            uint32_t af[3][4], bf[4][2];
            #pragma unroll
            for (int mt = 0; mt < 3; ++mt) {
                uint32_t addr = a0 + sw128((uint32_t)((rA + mt * 16) * 128
                                                      + (kk * 2 + cAsel) * 16));
                asm volatile("ldmatrix.sync.aligned.m8n8.x4.shared.b16 "
                             "{%0,%1,%2,%3}, [%4];"
                             : "=r"(af[mt][0]), "=r"(af[mt][1]),
                               "=r"(af[mt][2]), "=r"(af[mt][3]) : "r"(addr));
            }
            #pragma unroll
            for (int nt = 0; nt < 4; ++nt) {
                uint32_t addr = b0 + sw128((uint32_t)((rB + nt * 8) * 128
                                                      + (kk * 2 + cBsel) * 16));
                asm volatile("ldmatrix.sync.aligned.m8n8.x2.shared.b16 "
                             "{%0,%1}, [%2];"
                             : "=r"(bf[nt][0]), "=r"(bf[nt][1]) : "r"(addr));
            }
            #pragma unroll
            for (int mt = 0; mt < 3; ++mt)
                #pragma unroll
                for (int nt = 0; nt < 4; ++nt) {
                    asm volatile(
                        "mma.sync.aligned.m16n8k16.row.col.f32.bf16.bf16.f32 "
                        "{%0,%1,%2,%3}, {%4,%5,%6,%7}, {%8,%9}, {%0,%1,%2,%3};"
                        : "+f"(acc[mt][nt][0]), "+f"(acc[mt][nt][1]),
                          "+f"(acc[mt][nt][2]), "+f"(acc[mt][nt][3])
                        : "r"(af[mt][0]), "r"(af[mt][1]),
                          "r"(af[mt][2]), "r"(af[mt][3]),
                          "r"(bf[nt][0]), "r"(bf[nt][1]));
                }
        }
        if (kt + 1 < KT) {
            if (pf < KT) { asm volatile("cp.async.wait_group 1;"); }
            else         { asm volatile("cp.async.wait_group 0;"); }
        }
        __syncthreads();
        st = (st == 2) ? 0 : st + 1;
        pst = (pst == 2) ? 0 : pst + 1;
    }

    float* dst = g_NUM + ((size_t)ks * NB + b) * NQ * NM;
    int rowInTile = lane >> 2;
    int colInTile = (lane & 3) * 2;
    #pragma unroll
    for (int mt = 0; mt < 3; ++mt) {
        #pragma unroll
        for (int nt = 0; nt < 4; ++nt) {
            int qb = q0 + warpRow + mt * 16 + rowInTile;
            int mb = warpCol + nt * 8 + colInTile;
            #pragma unroll
            for (int r = 0; r < 4; ++r) {
                int q = qb + ((r >> 1) ? 8 : 0);
                int m = mb + (r & 1);
                if (q < NQ && m < NM)
                    dst[(size_t)q * NM + m] = acc[mt][nt][r];
            }
        }
    }
}

// ===================== kernel 3: assemble full cost matrix =====================
__global__ void __launch_bounds__(128) k_finalize(const float* __restrict__ logits,
                                                  const float* __restrict__ pboxes,
                                                  const int* __restrict__ glabels,
                                                  const float* __restrict__ gboxes,
                                                  float* __restrict__ out) {
    int q = blockIdx.x, b = blockIdx.y;
    int tid = threadIdx.x;
    __shared__ float probs[NCLS];
    __shared__ float red[128];

    const float* lg = logits + ((size_t)b * NQ + q) * NCLS;
    float x = (tid < NCLS) ? lg[tid] : -3.0e38f;
    red[tid] = x; __syncthreads();
    #pragma unroll
    for (int s = 64; s > 0; s >>= 1) { if (tid < s) red[tid] = fmaxf(red[tid], red[tid + s]); __syncthreads(); }
    float mx = red[0]; __syncthreads();
    float e = (tid < NCLS) ? __expf(x - mx) : 0.f;
    red[tid] = e; __syncthreads();
    #pragma unroll
    for (int s = 64; s > 0; s >>= 1) { if (tid < s) red[tid] += red[tid + s]; __syncthreads(); }
    float inv = 1.f / red[0];
    if (tid < NCLS) probs[tid] = e * inv;
    __syncthreads();

    const float* pb = pboxes + ((size_t)b * NQ + q) * 4;
    float px1 = pb[0], py1 = pb[1], px2 = pb[2], py2 = pb[3];
    float pa = (px2 - px1) * (py2 - py1);
    float psum = g_pm_sum[b * NQ + q];
    const size_t NSTR = (size_t)NB * NQ * NM;

    for (int m = tid; m < NM; m += 128) {
        int lbl = glabels[b * NM + m];
        float cclass = -probs[lbl];
        const float* gb = gboxes + ((size_t)b * NM + m) * 4;
        float gx1 = gb[0], gy1 = gb[1], gx2 = gb[2], gy2 = gb[3];
        float l1 = fabsf(px1 - gx1) + fabsf(py1 - gy1) + fabsf(px2 - gx2) + fabsf(py2 - gy2);
        float iw = fmaxf(fminf(px2, gx2) - fmaxf(px1, gx1), 0.f);
        float ih = fmaxf(fminf(py2, gy2) - fmaxf(py1, gy1), 0.f);
        float inter = iw * ih;
        float ga = (gx2 - gx1) * (gy2 - gy1);
        float uni = pa + ga - inter;
        float iou = inter / (uni + 1e-6f);
        float ew = fmaxf(fmaxf(px2, gx2) - fminf(px1, gx1), 0.f);
        float eh = fmaxf(fmaxf(py2, gy2) - fminf(py1, gy1), 0.f);
        float am = ew * eh;
        float giou = iou - (am - uni) / (am + 1e-6f);
        size_t ni = ((size_t)b * NQ + q) * NM + m;
        float dot = g_NUM[ni] + g_NUM[NSTR + ni] + g_NUM[2 * NSTR + ni] + g_NUM[3 * NSTR + ni];
        float den = psum + g_gm_sum[b * NM + m];
        float cmask = 1.f - (2.f * dot) / (den + 1e-6f);
        out[ni] = cclass + 5.f * (l1 - giou) + 2.f * cmask;
    }
}

// ===================== kernel 4: JV solver (round-12 exact, v=0 init) ==========
#define HUNG_THREADS 512
#define NQP 301                   // padded cost stride
#define HUNG_SMEM (NM * 4 + NM * NQP * 4 + NQ * 8 + NM * 8 + NM * 4)
#define NSLOT 10

__device__ __forceinline__ uint32_t fkey(float f) {
    uint32_t u = __float_as_uint(f);
    return (u & 0x80000000u) ? ~u : (u | 0x80000000u);
}
__device__ __forceinline__ float funkey(uint32_t k) {
    uint32_t u = (k & 0x80000000u) ? (k & 0x7fffffffu) : ~k;
    return __uint_as_float(u);
}
__device__ __forceinline__ uint32_t redux_min(uint32_t v) {
    uint32_t d;
    asm volatile("redux.sync.min.u32 %0, %1, 0xffffffff;" : "=r"(d) : "r"(v));
    return d;
}

__global__ void __launch_bounds__(HUNG_THREADS) k_hungarian(float* __restrict__ out, int out_size) {
    extern __shared__ char sm[];
    float* u    = reinterpret_cast<float*>(sm);               // [100]
    float* cost = u + NM;                                     // [100][301] transposed
    int* p      = reinterpret_cast<int*>(cost + NM * NQP);    // [300]
    int* way    = p + NQ;                                     // [300]
    int* flA    = way + NQ;                                   // [100]
    int* flB    = flA + NM;                                   // [100]
    int* rowarg = flB + NM;                                   // [100]

    int b = blockIdx.x;
    int tid = threadIdx.x;
    const int lane = tid & 31;
    const int warp = tid >> 5;
    const float* C = out + (size_t)b * NQ * NM;

    for (int idx = tid; idx < NM * NQ; idx += HUNG_THREADS) {
        int q = idx / NM, m = idx - q * NM;
        cost[m * NQP + q] = __ldg(C + idx);
    }
    for (int j = tid; j < NQ; j += HUNG_THREADS) p[j] = -1;
    __syncthreads();

    // ---- phase 1 (parallel): per-row minima across 16 warps ----
    const bool valid9 = (lane < 12);          // col 288..299 only
    for (int i = warp; i < NM; i += 16) {
        const float* crow = cost + i * NQP;
        float bv = 3.0e38f; int bi = 0x7fffffff;
        #pragma unroll
        for (int s = 0; s < NSLOT; ++s) {
            int col = s * 32 + lane;
            if (s < 9 || valid9) {
                float v = crow[col];
                if (v < bv) { bv = v; bi = col; }
            }
        }
        uint32_t k = fkey(bv);
        uint32_t mk = redux_min(k);
        int jstar = (int)redux_min((k == mk) ? (uint32_t)bi : 0xffffffffu);
        if (lane == 0) { u[i] = funkey(mk); rowarg[i] = jstar; }
    }
    __syncthreads();
    if (tid >= 32) return;

    float vv[NSLOT], minv[NSLOT];
    #pragma unroll
    for (int s = 0; s < NSLOT; ++s) vv[s] = 0.0f;

    // ---- greedy seed ----
    int nfree = 0;
    if (lane == 0) {
        for (int i = 0; i < NM; ++i) {
            int js = rowarg[i];
            if (p[js] == -1) p[js] = i;
            else flA[nfree++] = i;
        }
    }
    __syncwarp();
    nfree = __shfl_sync(0xffffffffu, nfree, 0);

    // ---- phase 2: augmenting row reduction (<=6 passes), shortened chain ----
    int* cur = flA; int* nxt = flB;
    for (int pass = 0; pass < 6 && nfree > 0; ++pass) {
        int nnew = 0;
        for (int k = 0; k < nfree; ++k) {
            int i = cur[k];
            for (;;) {
                const float* crow = cost + i * NQP;
                uint32_t kk[NSLOT];
                uint32_t m1k = 0xffffffffu, m2k = 0xffffffffu; int c1 = 0x7fffffff;
                #pragma unroll
                for (int s = 0; s < NSLOT; ++s) {
                    int col = s * 32 + lane;
                    uint32_t kv = 0xffffffffu;
                    if (s < 9 || valid9) kv = fkey(crow[col] - vv[s]);
                    kk[s] = kv;
                    if (kv < m1k) { m2k = m1k; m1k = kv; c1 = col; }
                    else if (kv < m2k) { m2k = kv; }
                }
                uint32_t u1k = redux_min(m1k);
                int j1 = (int)redux_min((m1k == u1k) ? (uint32_t)c1 : 0xffffffffu);
                uint32_t u2k = redux_min((m1k == u1k) ? m2k : m1k);
                unsigned tb = __ballot_sync(0xffffffffu, m1k == u1k);
                unsigned db = __ballot_sync(0xffffffffu, (m1k == u1k) && (m2k == u1k));
                if ((tb & (tb - 1)) || db) u2k = u1k;
                float u1 = funkey(u1k), u2 = funkey(u2k);
                bool strict = (u1k < u2k);
                int j2 = 0;
                if (!strict) {
                    int cbest = 0x7fffffff;
                    #pragma unroll
                    for (int s = 0; s < NSLOT; ++s) {
                        int col = s * 32 + lane;
                        if (kk[s] == u2k && col != j1 && col < cbest) cbest = col;
                    }
                    j2 = (int)redux_min((uint32_t)cbest);
                }

                int pack = 0;
                if (lane == 0) {
                    int jt = j1;
                    if (!strict) {
                        int pj1 = p[j1], pj2 = p[j2];
                        if (pj1 != -1 && pj2 == -1) jt = j2;
                    }
                    int ev = p[jt];
                    u[i] = u2; p[jt] = i;
                    pack = (jt << 9) | (ev + 1);
                }
                pack = __shfl_sync(0xffffffffu, pack, 0);
                int jt = pack >> 9;
                int ev = (pack & 511) - 1;
                if (strict && lane == (jt & 31)) vv[jt >> 5] -= (u2 - u1);

                if (ev == -1) break;
                if (strict) { i = ev; continue; }
                if (lane == 0) nxt[nnew] = ev;
                ++nnew;
                break;
            }
        }
        __syncwarp();
        int* t = cur; cur = nxt; nxt = t;
        nfree = nnew;
    }

    // ---- phase 3: shortest augmenting path for the remainder ----
    for (int fidx = 0; fidx < nfree; ++fidx) {
        int i = cur[fidx];
        unsigned usedmask = 0;
        #pragma unroll
        for (int s = 0; s < NSLOT; ++s) minv[s] = 3.0e38f;
        int cr = i, j0 = -1;

        while (true) {
            float ucr = u[cr];
            const float* crow = cost + cr * NQP;
            float bv = 3.0e38f; int bi = 0x7fffffff;
            #pragma unroll
            for (int s = 0; s < NSLOT; ++s) {
                int col = s * 32 + lane;
                bool ok = (s < 9 || valid9) && !((usedmask >> s) & 1u);
                if (ok) {
                    float cv = crow[col] - ucr - vv[s];
                    if (cv < minv[s]) { minv[s] = cv; way[col] = j0; }
                    if (minv[s] < bv) { bv = minv[s]; bi = col; }
                }
            }
            uint32_t k = fkey(bv);
            uint32_t mk = redux_min(k);
            float delta = funkey(mk);
            int j1 = (int)redux_min((k == mk) ? (uint32_t)bi : 0xffffffffu);

            #pragma unroll
            for (int s = 0; s < NSLOT; ++s) {
                int col = s * 32 + lane;
                if (s < 9 || valid9) {
                    if ((usedmask >> s) & 1u) {
                        u[p[col]] += delta;
                        vv[s] -= delta;
                    } else {
                        minv[s] -= delta;
                    }
                }
            }
            if (lane == 0) u[i] += delta;
            if (lane == (j1 & 31)) usedmask |= 1u << (j1 >> 5);
            j0 = j1;
            cr = p[j1];
            __syncwarp();
            if (cr == -1) break;
        }

        if (lane == 0) {
            int j = j0;
            while (j != -1) {
                int jp = way[j];
                p[j] = (jp != -1) ? p[jp] : i;
                j = jp;
            }
        }
        __syncwarp();
    }

    // ---- output: parallel compaction (ballot prefix ranks) ----
    if (out_size >= NB * NQ * NM + 2 * NB * NM) {
        float* pi = out + (size_t)NB * NQ * NM + (size_t)b * NM;
        float* gi = pi + (size_t)NB * NM;
        int base = 0;
        #pragma unroll
        for (int blk0 = 0; blk0 < NQ; blk0 += 32) {
            int col = blk0 + lane;
            int pv = (col < NQ) ? p[col] : -1;
            unsigned mask = __ballot_sync(0xffffffffu, pv >= 0);
            if (pv >= 0) {
                int r = base + __popc(mask & ((1u << lane) - 1u));
                pi[r] = (float)col;
                gi[r] = (float)pv;
            }
            base += __popc(mask);
        }
    }
}

// ===================== launch =====================
extern "C" void kernel_launch(void* const* d_in, const int* in_sizes, int n_in,
                              void* d_out, int out_size) {
    const float* pred_logits = (const float*)d_in[0];
    const float* pred_boxes  = (const float*)d_in[1];
    const float* pred_masks  = (const float*)d_in[2];
    const int*   gt_labels   = (const int*)d_in[3];
    const float* gt_boxes    = (const float*)d_in[4];
    const float* gt_masks    = (const float*)d_in[5];
    float* out = (float*)d_out;

    k_convert<<<NB * NQ + NB * NM, 256>>>(pred_masks, gt_masks);

    cudaFuncSetAttribute(k_mask_gemm, cudaFuncAttributeMaxDynamicSharedMemorySize, GEMM_SMEM);
    k_mask_gemm<<<dim3(NQT, NB, KSPLIT), 256, GEMM_SMEM>>>();

    k_finalize<<<dim3(NQ, NB), 128>>>(pred_logits, pred_boxes, gt_labels, gt_boxes, out);

    cudaFuncSetAttribute(k_hungarian, cudaFuncAttributeMaxDynamicSharedMemorySize, HUNG_SMEM);
    k_hungarian<<<NB, HUNG_THREADS, HUNG_SMEM>>>(out, out_size);
}

// round 16
// speedup vs baseline: 1.1031x; 1.0771x over previous
#include <cuda_runtime.h>
#include <cuda_bf16.h>
#include <cstdint>
#include <cstddef>

// ---------------- problem constants (fixed shapes) ----------------
#define NB 8
#define NQ 300
#define NM 100
#define NCLS 81
#define HW 16384
#define MPAD 128           // gt padded to 128 for N dim (row 100 = ones)
#define KSPLIT 4
#define KLEN (HW / KSPLIT) // 4096 elems per K-split
#define BK 64              // K chunk (elements) per iteration
#define KT (KLEN / BK)     // 64 iterations
#define MT 96              // M tile rows (queries per CTA)
#define NQT 4              // number of Q tiles

// ---------------- static device scratch (no allocations allowed) ----------------
__device__ __nv_bfloat16 g_GM[(size_t)NB * MPAD * HW];   // gt_masks bf16 (+ ones row 100)
__device__ float g_NUM[(size_t)KSPLIT * NB * NQ * NM];   // partial dot products
__device__ float g_PSUM[(size_t)KSPLIT * NB * NQ];       // partial pm row sums (ones col)
__device__ float g_gm_sum[NB * NM];

__device__ __forceinline__ float fast_sigmoid(float x) {
    float t;
    asm("tanh.approx.f32 %0, %1;" : "=f"(t) : "f"(x * 0.5f));
    return fmaf(t, 0.5f, 0.5f);
}

// ===================== kernel 1: gt -> bf16 convert + row sums + ones row =====================
__global__ void __launch_bounds__(256) k_convert_gt(const float* __restrict__ gm) {
    int bm = blockIdx.x;                       // 0..(NB*101-1)
    int b = bm / (NM + 1), m = bm - b * (NM + 1);
    uint4* dst = reinterpret_cast<uint4*>(g_GM + ((size_t)b * MPAD + m) * HW);
    if (m == NM) {                             // ones row (index 100)
        uint4 ones = make_uint4(0x3F803F80u, 0x3F803F80u, 0x3F803F80u, 0x3F803F80u);
        for (int i = threadIdx.x; i < HW / 8; i += 256) dst[i] = ones;
        return;
    }
    const float4* src = reinterpret_cast<const float4*>(gm + ((size_t)b * NM + m) * HW);
    float sum = 0.f;
    for (int i = threadIdx.x; i < HW / 8; i += 256) {
        float4 v0 = src[2 * i];
        float4 v1 = src[2 * i + 1];
        sum += ((v0.x + v0.y) + (v0.z + v0.w)) + ((v1.x + v1.y) + (v1.z + v1.w));
        __nv_bfloat162 p0 = __floats2bfloat162_rn(v0.x, v0.y);
        __nv_bfloat162 p1 = __floats2bfloat162_rn(v0.z, v0.w);
        __nv_bfloat162 p2 = __floats2bfloat162_rn(v1.x, v1.y);
        __nv_bfloat162 p3 = __floats2bfloat162_rn(v1.z, v1.w);
        dst[i] = make_uint4(*reinterpret_cast<uint32_t*>(&p0),
                            *reinterpret_cast<uint32_t*>(&p1),
                            *reinterpret_cast<uint32_t*>(&p2),
                            *reinterpret_cast<uint32_t*>(&p3));
    }
    for (int o = 16; o; o >>= 1) sum += __shfl_down_sync(0xffffffffu, sum, o);
    __shared__ float ws[8];
    if ((threadIdx.x & 31) == 0) ws[threadIdx.x >> 5] = sum;
    __syncthreads();
    if (threadIdx.x == 0) {
        float t = 0.f;
        #pragma unroll
        for (int w = 0; w < 8; ++w) t += ws[w];
        g_gm_sum[b * NM + m] = t;
    }
}

// ===================== kernel 2: fused sigmoid(A fp32) + mma.sync bf16 GEMM =====================
#define AF_TILE (MT * 64 * 4)     // fp32 staged A: 96 x 64 floats = 24576 B
#define AB_TILE (MT * 128)        // bf16 A tile: 96 x 128 B = 12288 B
#define B_TILE (128 * 128)        // 16384 B
#define SM_AF 0                   // 3 x AF_TILE
#define SM_B  (3 * AF_TILE)       // 3 x B_TILE
#define SM_AB (SM_B + 3 * B_TILE) // 2 x AB_TILE
#define GEMM_SMEM (SM_AB + 2 * AB_TILE)     // 147456

__device__ __forceinline__ uint32_t sw128(uint32_t off) {
    return off ^ ((off >> 3) & 0x70);
}

// stage fp32 A chunk: 96 rows x 64 floats; thread t copies i = t + s*256 (float4 granularity)
__device__ __forceinline__ void cp_tileA32(const float* __restrict__ Af, int q0,
                                           size_t kchunk, uint32_t dstBase) {
    int t = threadIdx.x;
    #pragma unroll
    for (int s = 0; s < 6; ++s) {
        int i = t + s * 256;                  // 0..1535
        int row = i >> 4, c4 = i & 15;
        int q = q0 + row; if (q > NQ - 1) q = NQ - 1;
        unsigned long long g =
            __cvta_generic_to_global(Af + (size_t)q * HW + kchunk + c4 * 4);
        asm volatile("cp.async.cg.shared.global [%0], [%1], 16;"
                     :: "r"(dstBase + (uint32_t)(i * 16)), "l"(g));
    }
}

// convert fp32 staged tile -> bf16 swizzled tile (each thread converts its own copies)
__device__ __forceinline__ void convert_tileA(const char* fsrc, char* bdst) {
    int t = threadIdx.x;
    #pragma unroll
    for (int s = 0; s < 6; ++s) {
        int i = t + s * 256;
        int row = i >> 4, c4 = i & 15;
        float4 v = *reinterpret_cast<const float4*>(fsrc + i * 16);
        float s0 = fast_sigmoid(v.x), s1 = fast_sigmoid(v.y);
        float s2 = fast_sigmoid(v.z), s3 = fast_sigmoid(v.w);
        __nv_bfloat162 lo = __floats2bfloat162_rn(s0, s1);
        __nv_bfloat162 hi = __floats2bfloat162_rn(s2, s3);
        uint32_t off = sw128((uint32_t)(row * 128 + c4 * 8));
        *reinterpret_cast<uint2*>(bdst + off) =
            make_uint2(*reinterpret_cast<uint32_t*>(&lo), *reinterpret_cast<uint32_t*>(&hi));
    }
}

__device__ __forceinline__ void cp_tileB(const __nv_bfloat16* __restrict__ src,
                                         uint32_t dstBase) {
    int t = threadIdx.x;
    #pragma unroll
    for (int s = 0; s < 4; ++s) {
        int i = t + s * 256;                  // 0..1023 (128 rows x 8 chunks)
        int row = i >> 3, c16 = i & 7;
        unsigned long long g =
            __cvta_generic_to_global(src + (size_t)row * HW + c16 * 8);
        uint32_t off = sw128((uint32_t)(row * 128 + c16 * 16));
        asm volatile("cp.async.cg.shared.global [%0], [%1], 16;"
                     :: "r"(dstBase + off), "l"(g));
    }
}

__global__ void __launch_bounds__(256, 1) k_mask_gemm(const float* __restrict__ pm) {
    extern __shared__ char smem[];
    uint32_t sAF = (uint32_t)__cvta_generic_to_shared(smem) + SM_AF;
    uint32_t sB  = (uint32_t)__cvta_generic_to_shared(smem) + SM_B;
    char* pAF = smem + SM_AF;
    char* pAB = smem + SM_AB;
    uint32_t sAB = (uint32_t)__cvta_generic_to_shared(smem) + SM_AB;

    int tid = threadIdx.x, lane = tid & 31, warp = tid >> 5;
    int wm = warp & 1, wn = warp >> 1;        // 2 x 4 warp grid
    int warpRow = wm * 48, warpCol = wn * 32;

    int tile = blockIdx.x, b = blockIdx.y, ks = blockIdx.z;
    int q0 = tile * MT;

    const float* Af = pm + (size_t)b * NQ * HW + (size_t)ks * KLEN;
    const __nv_bfloat16* Bbase = g_GM + (size_t)b * MPAD * HW + (size_t)ks * KLEN;

    float acc[3][4][4];
    #pragma unroll
    for (int i = 0; i < 3; ++i)
        #pragma unroll
        for (int j = 0; j < 4; ++j)
            #pragma unroll
            for (int r = 0; r < 4; ++r) acc[i][j][r] = 0.f;

    // prologue: stages 0 and 1 in flight
    cp_tileA32(Af, q0, 0, sAF);
    cp_tileB(Bbase, sB);
    asm volatile("cp.async.commit_group;");
    cp_tileA32(Af, q0, BK, sAF + AF_TILE);
    cp_tileB(Bbase + BK, sB + B_TILE);
    asm volatile("cp.async.commit_group;");
    asm volatile("cp.async.wait_group 1;");   // stage 0 arrived (per-thread)
    convert_tileA(pAF, pAB);                  // bf16 buffer 0 <- stage 0
    __syncthreads();

    int rA = warpRow + (lane & 15);
    int cAsel = lane >> 4;
    int rB = warpCol + (lane & 7);
    int cBsel = (lane >> 3) & 1;

    int stB = 0, stF = 0, pst = 2;            // B stage, fp32 stage (of current), prefetch stage
    for (int kt = 0; kt < KT; ++kt) {
        int pf = kt + 2;
        if (pf < KT) {
            cp_tileA32(Af, q0, (size_t)pf * BK, sAF + pst * AF_TILE);
            cp_tileB(Bbase + (size_t)pf * BK, sB + pst * B_TILE);
            asm volatile("cp.async.commit_group;");
            asm volatile("cp.async.wait_group 1;");   // stages <= kt+1 arrived
        } else if (kt + 1 < KT) {
            asm volatile("cp.async.wait_group 0;");
        }

        // convert next A stage into the other bf16 buffer (own-thread data, no barrier needed)
        if (kt + 1 < KT) {
            int nf = (stF == 2) ? 0 : stF + 1;
            convert_tileA(pAF + nf * AF_TILE, pAB + ((kt + 1) & 1) * AB_TILE);
        }

        uint32_t a0 = sAB + (kt & 1) * AB_TILE;
        uint32_t b0 = sB + stB * B_TILE;

        #pragma unroll
        for (int kk = 0; kk < 4; ++kk) {
            uint32_t af[3][4], bf[4][2];
            #pragma unroll
            for (int mt = 0; mt < 3; ++mt) {
                uint32_t addr = a0 + sw128((uint32_t)((rA + mt * 16) * 128
                                                      + (kk * 2 + cAsel) * 16));
                asm volatile("ldmatrix.sync.aligned.m8n8.x4.shared.b16 "
                             "{%0,%1,%2,%3}, [%4];"
                             : "=r"(af[mt][0]), "=r"(af[mt][1]),
                               "=r"(af[mt][2]), "=r"(af[mt][3]) : "r"(addr));
            }
            #pragma unroll
            for (int nt = 0; nt < 4; ++nt) {
                uint32_t addr = b0 + sw128((uint32_t)((rB + nt * 8) * 128
                                                      + (kk * 2 + cBsel) * 16));
                asm volatile("ldmatrix.sync.aligned.m8n8.x2.shared.b16 "
                             "{%0,%1}, [%2];"
                             : "=r"(bf[nt][0]), "=r"(bf[nt][1]) : "r"(addr));
            }
            #pragma unroll
            for (int mt = 0; mt < 3; ++mt)
                #pragma unroll
                for (int nt = 0; nt < 4; ++nt) {
                    asm volatile(
                        "mma.sync.aligned.m16n8k16.row.col.f32.bf16.bf16.f32 "
                        "{%0,%1,%2,%3}, {%4,%5,%6,%7}, {%8,%9}, {%0,%1,%2,%3};"
                        : "+f"(acc[mt][nt][0]), "+f"(acc[mt][nt][1]),
                          "+f"(acc[mt][nt][2]), "+f"(acc[mt][nt][3])
                        : "r"(af[mt][0]), "r"(af[mt][1]),
                          "r"(af[mt][2]), "r"(af[mt][3]),
                          "r"(bf[nt][0]), "r"(bf[nt][1]));
                }
        }
        __syncthreads();      // bf16 buffer (kt+1) + B stage kt+1 visible to all
        stB = (stB == 2) ? 0 : stB + 1;
        stF = (stF == 2) ? 0 : stF + 1;
        pst = (pst == 2) ? 0 : pst + 1;
    }

    // epilogue: m<100 -> g_NUM; m==100 (ones column) -> g_PSUM
    float* dst = g_NUM + ((size_t)ks * NB + b) * NQ * NM;
    float* psd = g_PSUM + ((size_t)ks * NB + b) * NQ;
    int rowInTile = lane >> 2;
    int colInTile = (lane & 3) * 2;
    #pragma unroll
    for (int mt = 0; mt < 3; ++mt) {
        #pragma unroll
        for (int nt = 0; nt < 4; ++nt) {
            int qb = q0 + warpRow + mt * 16 + rowInTile;
            int mb = warpCol + nt * 8 + colInTile;
            #pragma unroll
            for (int r = 0; r < 4; ++r) {
                int q = qb + ((r >> 1) ? 8 : 0);
                int m = mb + (r & 1);
                if (q < NQ) {
                    if (m < NM) dst[(size_t)q * NM + m] = acc[mt][nt][r];
                    else if (m == NM) psd[q] = acc[mt][nt][r];
                }
            }
        }
    }
}

// ===================== kernel 3: assemble full cost matrix =====================
__global__ void __launch_bounds__(128) k_finalize(const float* __restrict__ logits,
                                                  const float* __restrict__ pboxes,
                                                  const int* __restrict__ glabels,
                                                  const float* __restrict__ gboxes,
                                                  float* __restrict__ out) {
    int q = blockIdx.x, b = blockIdx.y;
    int tid = threadIdx.x;
    __shared__ float probs[NCLS];
    __shared__ float red[128];

    const float* lg = logits + ((size_t)b * NQ + q) * NCLS;
    float x = (tid < NCLS) ? lg[tid] : -3.0e38f;
    red[tid] = x; __syncthreads();
    #pragma unroll
    for (int s = 64; s > 0; s >>= 1) { if (tid < s) red[tid] = fmaxf(red[tid], red[tid + s]); __syncthreads(); }
    float mx = red[0]; __syncthreads();
    float e = (tid < NCLS) ? __expf(x - mx) : 0.f;
    red[tid] = e; __syncthreads();
    #pragma unroll
    for (int s = 64; s > 0; s >>= 1) { if (tid < s) red[tid] += red[tid + s]; __syncthreads(); }
    float inv = 1.f / red[0];
    if (tid < NCLS) probs[tid] = e * inv;
    __syncthreads();

    const float* pb = pboxes + ((size_t)b * NQ + q) * 4;
    float px1 = pb[0], py1 = pb[1], px2 = pb[2], py2 = pb[3];
    float pa = (px2 - px1) * (py2 - py1);
    float psum = g_PSUM[(0 * NB + b) * NQ + q] + g_PSUM[(1 * NB + b) * NQ + q]
               + g_PSUM[(2 * NB + b) * NQ + q] + g_PSUM[(3 * NB + b) * NQ + q];
    const size_t NSTR = (size_t)NB * NQ * NM;

    for (int m = tid; m < NM; m += 128) {
        int lbl = glabels[b * NM + m];
        float cclass = -probs[lbl];
        const float* gb = gboxes + ((size_t)b * NM + m) * 4;
        float gx1 = gb[0], gy1 = gb[1], gx2 = gb[2], gy2 = gb[3];
        float l1 = fabsf(px1 - gx1) + fabsf(py1 - gy1) + fabsf(px2 - gx2) + fabsf(py2 - gy2);
        float iw = fmaxf(fminf(px2, gx2) - fmaxf(px1, gx1), 0.f);
        float ih = fmaxf(fminf(py2, gy2) - fmaxf(py1, gy1), 0.f);
        float inter = iw * ih;
        float ga = (gx2 - gx1) * (gy2 - gy1);
        float uni = pa + ga - inter;
        float iou = inter / (uni + 1e-6f);
        float ew = fmaxf(fmaxf(px2, gx2) - fminf(px1, gx1), 0.f);
        float eh = fmaxf(fmaxf(py2, gy2) - fminf(py1, gy1), 0.f);
        float am = ew * eh;
        float giou = iou - (am - uni) / (am + 1e-6f);
        size_t ni = ((size_t)b * NQ + q) * NM + m;
        float dot = g_NUM[ni] + g_NUM[NSTR + ni] + g_NUM[2 * NSTR + ni] + g_NUM[3 * NSTR + ni];
        float den = psum + g_gm_sum[b * NM + m];
        float cmask = 1.f - (2.f * dot) / (den + 1e-6f);
        out[ni] = cclass + 5.f * (l1 - giou) + 2.f * cmask;
    }
}

// ===================== kernel 4: JV solver (round-12 exact, v=0 init) ==========
#define HUNG_THREADS 512
#define NQP 301                   // padded cost stride
#define HUNG_SMEM (NM * 4 + NM * NQP * 4 + NQ * 8 + NM * 8 + NM * 4)
#define NSLOT 10

__device__ __forceinline__ uint32_t fkey(float f) {
    uint32_t u = __float_as_uint(f);
    return (u & 0x80000000u) ? ~u : (u | 0x80000000u);
}
__device__ __forceinline__ float funkey(uint32_t k) {
    uint32_t u = (k & 0x80000000u) ? (k & 0x7fffffffu) : ~k;
    return __uint_as_float(u);
}
__device__ __forceinline__ uint32_t redux_min(uint32_t v) {
    uint32_t d;
    asm volatile("redux.sync.min.u32 %0, %1, 0xffffffff;" : "=r"(d) : "r"(v));
    return d;
}

__global__ void __launch_bounds__(HUNG_THREADS) k_hungarian(float* __restrict__ out, int out_size) {
    extern __shared__ char sm[];
    float* u    = reinterpret_cast<float*>(sm);               // [100]
    float* cost = u + NM;                                     // [100][301] transposed
    int* p      = reinterpret_cast<int*>(cost + NM * NQP);    // [300]
    int* way    = p + NQ;                                     // [300]
    int* flA    = way + NQ;                                   // [100]
    int* flB    = flA + NM;                                   // [100]
    int* rowarg = flB + NM;                                   // [100]

    int b = blockIdx.x;
    int tid = threadIdx.x;
    const int lane = tid & 31;
    const int warp = tid >> 5;
    const float* C = out + (size_t)b * NQ * NM;

    for (int idx = tid; idx < NM * NQ; idx += HUNG_THREADS) {
        int q = idx / NM, m = idx - q * NM;
        cost[m * NQP + q] = __ldg(C + idx);
    }
    for (int j = tid; j < NQ; j += HUNG_THREADS) p[j] = -1;
    __syncthreads();

    // ---- phase 1 (parallel): per-row minima across 16 warps ----
    const bool valid9 = (lane < 12);          // col 288..299 only
    for (int i = warp; i < NM; i += 16) {
        const float* crow = cost + i * NQP;
        float bv = 3.0e38f; int bi = 0x7fffffff;
        #pragma unroll
        for (int s = 0; s < NSLOT; ++s) {
            int col = s * 32 + lane;
            if (s < 9 || valid9) {
                float v = crow[col];
                if (v < bv) { bv = v; bi = col; }
            }
        }
        uint32_t k = fkey(bv);
        uint32_t mk = redux_min(k);
        int jstar = (int)redux_min((k == mk) ? (uint32_t)bi : 0xffffffffu);
        if (lane == 0) { u[i] = funkey(mk); rowarg[i] = jstar; }
    }
    __syncthreads();
    if (tid >= 32) return;

    float vv[NSLOT], minv[NSLOT];
    #pragma unroll
    for (int s = 0; s < NSLOT; ++s) vv[s] = 0.0f;

    // ---- greedy seed ----
    int nfree = 0;
    if (lane == 0) {
        for (int i = 0; i < NM; ++i) {
            int js = rowarg[i];
            if (p[js] == -1) p[js] = i;
            else flA[nfree++] = i;
        }
    }
    __syncwarp();
    nfree = __shfl_sync(0xffffffffu, nfree, 0);

    // ---- phase 2: augmenting row reduction (<=6 passes), shortened chain ----
    int* cur = flA; int* nxt = flB;
    for (int pass = 0; pass < 6 && nfree > 0; ++pass) {
        int nnew = 0;
        for (int k = 0; k < nfree; ++k) {
            int i = cur[k];
            for (;;) {
                const float* crow = cost + i * NQP;
                uint32_t kk[NSLOT];
                uint32_t m1k = 0xffffffffu, m2k = 0xffffffffu; int c1 = 0x7fffffff;
                #pragma unroll
                for (int s = 0; s < NSLOT; ++s) {
                    int col = s * 32 + lane;
                    uint32_t kv = 0xffffffffu;
                    if (s < 9 || valid9) kv = fkey(crow[col] - vv[s]);
                    kk[s] = kv;
                    if (kv < m1k) { m2k = m1k; m1k = kv; c1 = col; }
                    else if (kv < m2k) { m2k = kv; }
                }
                uint32_t u1k = redux_min(m1k);
                int j1 = (int)redux_min((m1k == u1k) ? (uint32_t)c1 : 0xffffffffu);
                uint32_t u2k = redux_min((m1k == u1k) ? m2k : m1k);
                unsigned tb = __ballot_sync(0xffffffffu, m1k == u1k);
                unsigned db = __ballot_sync(0xffffffffu, (m1k == u1k) && (m2k == u1k));
                if ((tb & (tb - 1)) || db) u2k = u1k;
                float u1 = funkey(u1k), u2 = funkey(u2k);
                bool strict = (u1k < u2k);
                int j2 = 0;
                if (!strict) {
                    int cbest = 0x7fffffff;
                    #pragma unroll
                    for (int s = 0; s < NSLOT; ++s) {
                        int col = s * 32 + lane;
                        if (kk[s] == u2k && col != j1 && col < cbest) cbest = col;
                    }
                    j2 = (int)redux_min((uint32_t)cbest);
                }

                int pack = 0;
                if (lane == 0) {
                    int jt = j1;
                    if (!strict) {
                        int pj1 = p[j1], pj2 = p[j2];
                        if (pj1 != -1 && pj2 == -1) jt = j2;
                    }
                    int ev = p[jt];
                    u[i] = u2; p[jt] = i;
                    pack = (jt << 9) | (ev + 1);
                }
                pack = __shfl_sync(0xffffffffu, pack, 0);
                int jt = pack >> 9;
                int ev = (pack & 511) - 1;
                if (strict && lane == (jt & 31)) vv[jt >> 5] -= (u2 - u1);

                if (ev == -1) break;
                if (strict) { i = ev; continue; }
                if (lane == 0) nxt[nnew] = ev;
                ++nnew;
                break;
            }
        }
        __syncwarp();
        int* t = cur; cur = nxt; nxt = t;
        nfree = nnew;
    }

    // ---- phase 3: shortest augmenting path for the remainder ----
    for (int fidx = 0; fidx < nfree; ++fidx) {
        int i = cur[fidx];
        unsigned usedmask = 0;
        #pragma unroll
        for (int s = 0; s < NSLOT; ++s) minv[s] = 3.0e38f;
        int cr = i, j0 = -1;

        while (true) {
            float ucr = u[cr];
            const float* crow = cost + cr * NQP;
            float bv = 3.0e38f; int bi = 0x7fffffff;
            #pragma unroll
            for (int s = 0; s < NSLOT; ++s) {
                int col = s * 32 + lane;
                bool ok = (s < 9 || valid9) && !((usedmask >> s) & 1u);
                if (ok) {
                    float cv = crow[col] - ucr - vv[s];
                    if (cv < minv[s]) { minv[s] = cv; way[col] = j0; }
                    if (minv[s] < bv) { bv = minv[s]; bi = col; }
                }
            }
            uint32_t k = fkey(bv);
            uint32_t mk = redux_min(k);
            float delta = funkey(mk);
            int j1 = (int)redux_min((k == mk) ? (uint32_t)bi : 0xffffffffu);

            #pragma unroll
            for (int s = 0; s < NSLOT; ++s) {
                int col = s * 32 + lane;
                if (s < 9 || valid9) {
                    if ((usedmask >> s) & 1u) {
                        u[p[col]] += delta;
                        vv[s] -= delta;
                    } else {
                        minv[s] -= delta;
                    }
                }
            }
            if (lane == 0) u[i] += delta;
            if (lane == (j1 & 31)) usedmask |= 1u << (j1 >> 5);
            j0 = j1;
            cr = p[j1];
            __syncwarp();
            if (cr == -1) break;
        }

        if (lane == 0) {
            int j = j0;
            while (j != -1) {
                int jp = way[j];
                p[j] = (jp != -1) ? p[jp] : i;
                j = jp;
            }
        }
        __syncwarp();
    }

    // ---- output: parallel compaction (ballot prefix ranks) ----
    if (out_size >= NB * NQ * NM + 2 * NB * NM) {
        float* pi = out + (size_t)NB * NQ * NM + (size_t)b * NM;
        float* gi = pi + (size_t)NB * NM;
        int base = 0;
        #pragma unroll
        for (int blk0 = 0; blk0 < NQ; blk0 += 32) {
            int col = blk0 + lane;
            int pv = (col < NQ) ? p[col] : -1;
            unsigned mask = __ballot_sync(0xffffffffu, pv >= 0);
            if (pv >= 0) {
                int r = base + __popc(mask & ((1u << lane) - 1u));
                pi[r] = (float)col;
                gi[r] = (float)pv;
            }
            base += __popc(mask);
        }
    }
}

// ===================== launch =====================
extern "C" void kernel_launch(void* const* d_in, const int* in_sizes, int n_in,
                              void* d_out, int out_size) {
    const float* pred_logits = (const float*)d_in[0];
    const float* pred_boxes  = (const float*)d_in[1];
    const float* pred_masks  = (const float*)d_in[2];
    const int*   gt_labels   = (const int*)d_in[3];
    const float* gt_boxes    = (const float*)d_in[4];
    const float* gt_masks    = (const float*)d_in[5];
    float* out = (float*)d_out;

    k_convert_gt<<<NB * (NM + 1), 256>>>(gt_masks);

    cudaFuncSetAttribute(k_mask_gemm, cudaFuncAttributeMaxDynamicSharedMemorySize, GEMM_SMEM);
    k_mask_gemm<<<dim3(NQT, NB, KSPLIT), 256, GEMM_SMEM>>>(pred_masks);

    k_finalize<<<dim3(NQ, NB), 128>>>(pred_logits, pred_boxes, gt_labels, gt_boxes, out);

    cudaFuncSetAttribute(k_hungarian, cudaFuncAttributeMaxDynamicSharedMemorySize, HUNG_SMEM);
    k_hungarian<<<NB, HUNG_THREADS, HUNG_SMEM>>>(out, out_size);
}